// round 2
// baseline (speedup 1.0000x reference)
#include <cuda_runtime.h>
#include <cstdint>

#define N_NODES 100000
#define N_EDGES 1600000
#define IN_CH   512
#define HID_CH  256
#define OUT_CH  64
#define K_STEPS 10

// ---------------- scratch (static __device__, no allocation) ----------------
__device__ int   g_deg[N_NODES];
__device__ int   g_cursor[N_NODES];
__device__ float g_dinv[N_NODES];
__device__ int   g_rowptr[N_NODES + 1];
__device__ int   g_csrc [N_EDGES + N_NODES];
__device__ float g_cnorm[N_EDGES + N_NODES];
__device__ __align__(16) float g_hid [(size_t)N_NODES * HID_CH];
__device__ __align__(16) float g_h0  [(size_t)N_NODES * OUT_CH];
__device__ __align__(16) float g_htmp[(size_t)N_NODES * OUT_CH];

// ---------------- preprocessing kernels ----------------
__global__ void init_deg_cursor()
{
    int i = blockIdx.x * blockDim.x + threadIdx.x;
    if (i < N_NODES) { g_deg[i] = 1; g_cursor[i] = 0; }  // deg starts at 1 (self-loop)
}

// edge_index is int32, layout [2, E]: src row then dst row
__global__ void count_deg(const int* __restrict__ ei)
{
    int e = blockIdx.x * blockDim.x + threadIdx.x;
    if (e < N_EDGES) {
        int d = ei[N_EDGES + e];   // dst
        if ((unsigned)d < N_NODES) atomicAdd(&g_deg[d], 1);
    }
}

__global__ void compute_dinv()
{
    int i = blockIdx.x * blockDim.x + threadIdx.x;
    if (i < N_NODES) g_dinv[i] = rsqrtf((float)g_deg[i]);
}

// single-block exclusive scan of g_deg -> g_rowptr (100k elements, 1024 threads)
__global__ void scan_rowptr()
{
    __shared__ int ssum[1024];
    const int t = threadIdx.x;
    const int CH = (N_NODES + 1023) / 1024;   // 98
    int begin = t * CH;
    int end   = begin + CH; if (end > N_NODES) end = N_NODES;
    int s = 0;
    for (int i = begin; i < end; i++) s += g_deg[i];
    ssum[t] = s;
    __syncthreads();
    for (int off = 1; off < 1024; off <<= 1) {
        int other = 0;
        if (t >= off) other = ssum[t - off];
        __syncthreads();
        if (t >= off) ssum[t] += other;
        __syncthreads();
    }
    int run = (t == 0) ? 0 : ssum[t - 1];
    for (int i = begin; i < end; i++) {
        g_rowptr[i] = run;
        run += g_deg[i];
    }
    if (end == N_NODES) g_rowptr[N_NODES] = run;
}

// scatter edges + self-loops into CSR (by dst), with precomputed norm
__global__ void fill_csr(const int* __restrict__ ei)
{
    int idx = blockIdx.x * blockDim.x + threadIdx.x;
    if (idx < N_EDGES) {
        int s = ei[idx];
        int d = ei[N_EDGES + idx];
        if ((unsigned)s >= N_NODES || (unsigned)d >= N_NODES) return;
        int pos = g_rowptr[d] + atomicAdd(&g_cursor[d], 1);
        g_csrc[pos]  = s;
        g_cnorm[pos] = g_dinv[s] * g_dinv[d];
    } else if (idx < N_EDGES + N_NODES) {
        int v = idx - N_EDGES;
        int pos = g_rowptr[v] + atomicAdd(&g_cursor[v], 1);
        g_csrc[pos]  = v;
        float dv = g_dinv[v];
        g_cnorm[pos] = dv * dv;
    }
}

// ---------------- tf32 tensor-core GEMM: C = A(MxK) * B(KxN) + bias, opt relu ----------------
__device__ __forceinline__ unsigned f2tf32(float f)
{
    unsigned r;
    asm("cvt.rna.tf32.f32 %0, %1;" : "=r"(r) : "f"(f));
    return r;
}

#define MMA_TF32(d, a, b)                                                        \
    asm volatile("mma.sync.aligned.m16n8k8.row.col.f32.tf32.tf32.f32 "           \
                 "{%0,%1,%2,%3},{%4,%5,%6,%7},{%8,%9},{%0,%1,%2,%3};\n"          \
                 : "+f"(d[0]), "+f"(d[1]), "+f"(d[2]), "+f"(d[3])                \
                 : "r"(a[0]), "r"(a[1]), "r"(a[2]), "r"(a[3]),                   \
                   "r"(b[0]), "r"(b[1]))

// BM=128, BN=64, BK=16, 256 threads (8 warps, 4x2), warp tile 32x32
template<bool RELU>
__global__ __launch_bounds__(256) void gemm_kernel(
    const float* __restrict__ A, const float* __restrict__ B,
    const float* __restrict__ bias, float* __restrict__ C,
    int M, int N, int Kd)
{
    const int BM = 128, BN = 64, BK = 16;
    __shared__ float As[BM][BK + 4];
    __shared__ float Bs[BK][BN + 8];

    int tid  = threadIdx.x;
    int warp = tid >> 5, lane = tid & 31;
    int wm = warp >> 1;        // 0..3
    int wn = warp & 1;         // 0..1
    int bm0 = blockIdx.x * BM;
    int bn0 = blockIdx.y * BN;

    float acc[2][4][4];
    #pragma unroll
    for (int i = 0; i < 2; i++)
        #pragma unroll
        for (int j = 0; j < 4; j++)
            #pragma unroll
            for (int l = 0; l < 4; l++) acc[i][j][l] = 0.0f;

    for (int k0 = 0; k0 < Kd; k0 += BK) {
        float4 ra[2];
        #pragma unroll
        for (int i = 0; i < 2; i++) {
            int idx = tid + i * 256;
            int row = idx >> 2, c4 = idx & 3;
            int gr = bm0 + row;
            if (gr < M) ra[i] = *(const float4*)&A[(size_t)gr * Kd + k0 + c4 * 4];
            else        ra[i] = make_float4(0.f, 0.f, 0.f, 0.f);
        }
        int brow = tid >> 4, bc4 = tid & 15;
        float4 rb = *(const float4*)&B[(size_t)(k0 + brow) * N + bn0 + bc4 * 4];

        __syncthreads();
        #pragma unroll
        for (int i = 0; i < 2; i++) {
            int idx = tid + i * 256;
            int row = idx >> 2, c4 = idx & 3;
            *(float4*)&As[row][c4 * 4] = ra[i];
        }
        *(float4*)&Bs[brow][bc4 * 4] = rb;
        __syncthreads();

        #pragma unroll
        for (int kc = 0; kc < 2; kc++) {
            unsigned a[2][4], b[4][2];
            #pragma unroll
            for (int mt = 0; mt < 2; mt++) {
                int r = wm * 32 + mt * 16 + (lane >> 2);
                int c = kc * 8 + (lane & 3);
                a[mt][0] = f2tf32(As[r][c]);
                a[mt][1] = f2tf32(As[r + 8][c]);
                a[mt][2] = f2tf32(As[r][c + 4]);
                a[mt][3] = f2tf32(As[r + 8][c + 4]);
            }
            #pragma unroll
            for (int nt = 0; nt < 4; nt++) {
                int col = wn * 32 + nt * 8 + (lane >> 2);
                int kr  = kc * 8 + (lane & 3);
                b[nt][0] = f2tf32(Bs[kr][col]);
                b[nt][1] = f2tf32(Bs[kr + 4][col]);
            }
            #pragma unroll
            for (int mt = 0; mt < 2; mt++)
                #pragma unroll
                for (int nt = 0; nt < 4; nt++)
                    MMA_TF32(acc[mt][nt], a[mt], b[nt]);
        }
    }

    #pragma unroll
    for (int mt = 0; mt < 2; mt++) {
        #pragma unroll
        for (int nt = 0; nt < 4; nt++) {
            int r0 = bm0 + wm * 32 + mt * 16 + (lane >> 2);
            int c0 = bn0 + wn * 32 + nt * 8 + (lane & 3) * 2;
            float bv0 = bias[c0], bv1 = bias[c0 + 1];
            #pragma unroll
            for (int h = 0; h < 2; h++) {
                int r = r0 + h * 8;
                if (r < M) {
                    float v0 = acc[mt][nt][h * 2 + 0] + bv0;
                    float v1 = acc[mt][nt][h * 2 + 1] + bv1;
                    if (RELU) { v0 = fmaxf(v0, 0.f); v1 = fmaxf(v1, 0.f); }
                    C[(size_t)r * N + c0]     = v0;
                    C[(size_t)r * N + c0 + 1] = v1;
                }
            }
        }
    }
}

// ---------------- propagation: h_out = 0.9 * (A_norm @ h_in) + 0.1 * h0 ----------------
// 16 threads per node, each owns 4 channels (one float4) of the 64-ch feature.
__global__ __launch_bounds__(256) void prop_kernel(
    const float* __restrict__ hin, float* __restrict__ hout,
    const float* __restrict__ h0)
{
    int gt = blockIdx.x * blockDim.x + threadIdx.x;
    int v = gt >> 4;
    if (v >= N_NODES) return;
    int lane = gt & 15;

    int e0 = g_rowptr[v];
    int e1 = g_rowptr[v + 1];
    const float4* h4 = (const float4*)hin;

    float4 acc = make_float4(0.f, 0.f, 0.f, 0.f);
    #pragma unroll 4
    for (int e = e0; e < e1; e++) {
        int   s = g_csrc[e];
        float w = g_cnorm[e];
        float4 hv = h4[(size_t)s * 16 + lane];
        acc.x = fmaf(w, hv.x, acc.x);
        acc.y = fmaf(w, hv.y, acc.y);
        acc.z = fmaf(w, hv.z, acc.z);
        acc.w = fmaf(w, hv.w, acc.w);
    }
    float4 z = ((const float4*)h0)[(size_t)v * 16 + lane];
    float4 r;
    r.x = 0.9f * acc.x + 0.1f * z.x;
    r.y = 0.9f * acc.y + 0.1f * z.y;
    r.z = 0.9f * acc.z + 0.1f * z.z;
    r.w = 0.9f * acc.w + 0.1f * z.w;
    ((float4*)hout)[(size_t)v * 16 + lane] = r;
}

// ---------------- launch ----------------
extern "C" void kernel_launch(void* const* d_in, const int* in_sizes, int n_in,
                              void* d_out, int out_size)
{
    const float* x  = (const float*)d_in[0];
    const int*   ei = (const int*)d_in[1];     // int32 [2, E]
    const float* w1 = (const float*)d_in[2];
    const float* b1 = (const float*)d_in[3];
    const float* w2 = (const float*)d_in[4];
    const float* b2 = (const float*)d_in[5];
    float*       out = (float*)d_out;

    float *p_hid, *p_h0, *p_htmp;
    cudaGetSymbolAddress((void**)&p_hid,  g_hid);
    cudaGetSymbolAddress((void**)&p_h0,   g_h0);
    cudaGetSymbolAddress((void**)&p_htmp, g_htmp);

    // graph preprocessing (CSR by dst, with self-loops and GCN norms)
    init_deg_cursor<<<(N_NODES + 255) / 256, 256>>>();
    count_deg<<<(N_EDGES + 255) / 256, 256>>>(ei);
    compute_dinv<<<(N_NODES + 255) / 256, 256>>>();
    scan_rowptr<<<1, 1024>>>();
    fill_csr<<<(N_EDGES + N_NODES + 255) / 256, 256>>>(ei);

    // MLP: h0 = relu(x @ w1 + b1) @ w2 + b2
    dim3 g1((N_NODES + 127) / 128, HID_CH / 64);
    gemm_kernel<true><<<g1, 256>>>(x, w1, b1, p_hid, N_NODES, HID_CH, IN_CH);
    dim3 g2((N_NODES + 127) / 128, OUT_CH / 64);
    gemm_kernel<false><<<g2, 256>>>(p_hid, w2, b2, p_h0, N_NODES, OUT_CH, HID_CH);

    // APPNP propagation: K=10 steps, ping-pong so the last (odd) step hits d_out
    const float* cur = p_h0;
    int grid = (N_NODES * 16 + 255) / 256;
    for (int s = 0; s < K_STEPS; s++) {
        float* o = (s & 1) ? out : p_htmp;
        prop_kernel<<<grid, 256>>>(cur, o, p_h0);
        cur = o;
    }
}

// round 3
// speedup vs baseline: 1.0903x; 1.0903x over previous
#include <cuda_runtime.h>
#include <cstdint>

#define N_NODES 100000
#define N_EDGES 1600000
#define IN_CH   512
#define HID_CH  256
#define OUT_CH  64
#define K_STEPS 10
#define NB_SCAN ((N_NODES + 255) / 256)   // 391

// ---------------- scratch (static __device__, no allocation) ----------------
__device__ int   g_deg[N_NODES];          // degree incl. self-loop (for norm)
__device__ int   g_cursor[N_NODES];
__device__ float g_dinv[N_NODES];
__device__ float g_selfw[N_NODES];        // 0.9 * dinv^2
__device__ int   g_rowptr[N_NODES + 1];   // edge-only CSR
__device__ int   g_part[NB_SCAN];
__device__ __align__(16) int2  g_epack[N_EDGES];   // {src, bitcast(0.9*norm)}
__device__ __align__(16) float g_hid [(size_t)N_NODES * HID_CH];
__device__ __align__(16) float g_h0  [(size_t)N_NODES * OUT_CH];
__device__ __align__(16) float g_htmp[(size_t)N_NODES * OUT_CH];

// ---------------- preprocessing ----------------
__global__ void init_deg_cursor()
{
    int i = blockIdx.x * blockDim.x + threadIdx.x;
    if (i < N_NODES) { g_deg[i] = 1; g_cursor[i] = 0; }   // self-loop counted in deg
}

__global__ void count_deg(const int* __restrict__ ei)
{
    int e = blockIdx.x * blockDim.x + threadIdx.x;
    if (e < N_EDGES) {
        int d = ei[N_EDGES + e];
        if ((unsigned)d < N_NODES) atomicAdd(&g_deg[d], 1);
    }
}

__global__ void compute_dinv()
{
    int i = blockIdx.x * blockDim.x + threadIdx.x;
    if (i < N_NODES) {
        float dv = rsqrtf((float)g_deg[i]);
        g_dinv[i]  = dv;
        g_selfw[i] = 0.9f * dv * dv;
    }
}

// ---- fast 3-phase exclusive scan of edge-only degree (deg-1) into g_rowptr ----
__global__ void scan_p1()
{
    int b = blockIdx.x, t = threadIdx.x;
    int i = b * 256 + t;
    int v = (i < N_NODES) ? (g_deg[i] - 1) : 0;
    int lane = t & 31, w = t >> 5;
    int x = v;
    #pragma unroll
    for (int o = 1; o < 32; o <<= 1) {
        int y = __shfl_up_sync(0xffffffffu, x, o);
        if (lane >= o) x += y;
    }
    __shared__ int wsum[8];
    if (lane == 31) wsum[w] = x;
    __syncthreads();
    if (t < 8) {
        int s = wsum[t];
        #pragma unroll
        for (int o = 1; o < 8; o <<= 1) {
            int y = __shfl_up_sync(0xffu, s, o);
            if (t >= o) s += y;
        }
        wsum[t] = s;   // inclusive across warps
    }
    __syncthreads();
    int base = (w > 0) ? wsum[w - 1] : 0;
    if (i < N_NODES) g_rowptr[i] = base + x - v;   // block-local exclusive
    if (t == 255) g_part[b] = wsum[7];             // block total
}

__global__ void scan_p2()
{
    __shared__ int s[512];
    int t = threadIdx.x;
    int v = (t < NB_SCAN) ? g_part[t] : 0;
    s[t] = v;
    __syncthreads();
    for (int o = 1; o < 512; o <<= 1) {
        int y = (t >= o) ? s[t - o] : 0;
        __syncthreads();
        s[t] += y;
        __syncthreads();
    }
    if (t < NB_SCAN) g_part[t] = s[t] - v;         // exclusive
    if (t == NB_SCAN - 1) g_rowptr[N_NODES] = s[t]; // grand total
}

__global__ void scan_p3()
{
    int b = blockIdx.x, t = threadIdx.x;
    int i = b * 256 + t;
    if (i < N_NODES) g_rowptr[i] += g_part[b];
}

// scatter edges into CSR (by dst) as packed {src, weight}
__global__ void fill_csr(const int* __restrict__ ei)
{
    int idx = blockIdx.x * blockDim.x + threadIdx.x;
    if (idx < N_EDGES) {
        int s = ei[idx];
        int d = ei[N_EDGES + idx];
        if ((unsigned)s >= N_NODES || (unsigned)d >= N_NODES) return;
        int pos = g_rowptr[d] + atomicAdd(&g_cursor[d], 1);
        int2 p;
        p.x = s;
        p.y = __float_as_int(0.9f * g_dinv[s] * g_dinv[d]);
        g_epack[pos] = p;
    }
}

// ---------------- tf32 tensor-core GEMM ----------------
__device__ __forceinline__ unsigned f2tf32(float f)
{
    unsigned r;
    asm("cvt.rna.tf32.f32 %0, %1;" : "=r"(r) : "f"(f));
    return r;
}

#define MMA_TF32(d, a, b)                                                        \
    asm volatile("mma.sync.aligned.m16n8k8.row.col.f32.tf32.tf32.f32 "           \
                 "{%0,%1,%2,%3},{%4,%5,%6,%7},{%8,%9},{%0,%1,%2,%3};\n"          \
                 : "+f"(d[0]), "+f"(d[1]), "+f"(d[2]), "+f"(d[3])                \
                 : "r"(a[0]), "r"(a[1]), "r"(a[2]), "r"(a[3]),                   \
                   "r"(b[0]), "r"(b[1]))

// BM=128, BN=64, BK=16, 256 threads (8 warps, 4x2 -> warp tile 32x32)
// Double-buffered smem (tf32 pre-converted), gmem loads pipelined in regs.
template<bool RELU>
__global__ __launch_bounds__(256) void gemm_kernel(
    const float* __restrict__ A, const float* __restrict__ B,
    const float* __restrict__ bias, float* __restrict__ C,
    int M, int N, int Kd)
{
    const int BM = 128, BN = 64, BK = 16;
    __shared__ unsigned As[2][BM][BK + 4];
    __shared__ unsigned Bs[2][BK][BN + 8];

    int tid  = threadIdx.x;
    int warp = tid >> 5, lane = tid & 31;
    int wm = warp >> 1;
    int wn = warp & 1;
    int bm0 = blockIdx.x * BM;
    int bn0 = blockIdx.y * BN;

    // per-thread staging coords
    int arow = tid >> 2, ac4 = tid & 3;          // A: 2 chunks of 64 rows
    int brow = tid >> 4, bc4 = tid & 15;

    float acc[2][4][4];
    #pragma unroll
    for (int i = 0; i < 2; i++)
        #pragma unroll
        for (int j = 0; j < 4; j++)
            #pragma unroll
            for (int l = 0; l < 4; l++) acc[i][j][l] = 0.0f;

    float4 ra[2], rb;
    auto load_tile = [&](int k0) {
        #pragma unroll
        for (int i = 0; i < 2; i++) {
            int gr = bm0 + arow + i * 64;
            if (gr < M) ra[i] = *(const float4*)&A[(size_t)gr * Kd + k0 + ac4 * 4];
            else        ra[i] = make_float4(0.f, 0.f, 0.f, 0.f);
        }
        rb = *(const float4*)&B[(size_t)(k0 + brow) * N + bn0 + bc4 * 4];
    };
    auto store_tile = [&](int buf) {
        #pragma unroll
        for (int i = 0; i < 2; i++) {
            unsigned* p = &As[buf][arow + i * 64][ac4 * 4];
            p[0] = f2tf32(ra[i].x); p[1] = f2tf32(ra[i].y);
            p[2] = f2tf32(ra[i].z); p[3] = f2tf32(ra[i].w);
        }
        unsigned* q = &Bs[buf][brow][bc4 * 4];
        q[0] = f2tf32(rb.x); q[1] = f2tf32(rb.y);
        q[2] = f2tf32(rb.z); q[3] = f2tf32(rb.w);
    };

    load_tile(0);
    store_tile(0);
    __syncthreads();

    int nIter = Kd / BK;
    for (int it = 0; it < nIter; it++) {
        int cur = it & 1;
        if (it + 1 < nIter) load_tile((it + 1) * BK);

        #pragma unroll
        for (int kc = 0; kc < 2; kc++) {
            unsigned a[2][4], b[4][2];
            #pragma unroll
            for (int mt = 0; mt < 2; mt++) {
                int r = wm * 32 + mt * 16 + (lane >> 2);
                int c = kc * 8 + (lane & 3);
                a[mt][0] = As[cur][r][c];
                a[mt][1] = As[cur][r + 8][c];
                a[mt][2] = As[cur][r][c + 4];
                a[mt][3] = As[cur][r + 8][c + 4];
            }
            #pragma unroll
            for (int nt = 0; nt < 4; nt++) {
                int col = wn * 32 + nt * 8 + (lane >> 2);
                int kr  = kc * 8 + (lane & 3);
                b[nt][0] = Bs[cur][kr][col];
                b[nt][1] = Bs[cur][kr + 4][col];
            }
            #pragma unroll
            for (int mt = 0; mt < 2; mt++)
                #pragma unroll
                for (int nt = 0; nt < 4; nt++)
                    MMA_TF32(acc[mt][nt], a[mt], b[nt]);
        }

        if (it + 1 < nIter) {
            store_tile(1 - cur);
            __syncthreads();
        }
    }

    #pragma unroll
    for (int mt = 0; mt < 2; mt++) {
        #pragma unroll
        for (int nt = 0; nt < 4; nt++) {
            int r0 = bm0 + wm * 32 + mt * 16 + (lane >> 2);
            int c0 = bn0 + wn * 32 + nt * 8 + (lane & 3) * 2;
            float bv0 = bias[c0], bv1 = bias[c0 + 1];
            #pragma unroll
            for (int h = 0; h < 2; h++) {
                int r = r0 + h * 8;
                if (r < M) {
                    float v0 = acc[mt][nt][h * 2 + 0] + bv0;
                    float v1 = acc[mt][nt][h * 2 + 1] + bv1;
                    if (RELU) { v0 = fmaxf(v0, 0.f); v1 = fmaxf(v1, 0.f); }
                    C[(size_t)r * N + c0]     = v0;
                    C[(size_t)r * N + c0 + 1] = v1;
                }
            }
        }
    }
}

// ---------------- propagation ----------------
// h_out = sum_e w_e * h_in[src_e]  (w pre-scaled by 0.9)
//       + selfw[v] * h_in[v] + 0.1 * h0[v]
// 16 threads per node, each owns one float4 (4 channels) of the 64-ch feature.
__global__ __launch_bounds__(256) void prop_kernel(
    const float* __restrict__ hin, float* __restrict__ hout,
    const float* __restrict__ h0)
{
    int gt = blockIdx.x * blockDim.x + threadIdx.x;
    int v = gt >> 4;
    if (v >= N_NODES) return;
    int lane = gt & 15;

    int e0 = g_rowptr[v];
    int e1 = g_rowptr[v + 1];
    const float4* h4 = (const float4*)hin;

    float4 acc = make_float4(0.f, 0.f, 0.f, 0.f);
    int e = e0;
    for (; e + 2 <= e1; e += 2) {
        int2 p0 = __ldg(&g_epack[e]);
        int2 p1 = __ldg(&g_epack[e + 1]);
        float4 hv0 = h4[(size_t)p0.x * 16 + lane];
        float4 hv1 = h4[(size_t)p1.x * 16 + lane];
        float w0 = __int_as_float(p0.y);
        float w1 = __int_as_float(p1.y);
        acc.x = fmaf(w0, hv0.x, acc.x); acc.y = fmaf(w0, hv0.y, acc.y);
        acc.z = fmaf(w0, hv0.z, acc.z); acc.w = fmaf(w0, hv0.w, acc.w);
        acc.x = fmaf(w1, hv1.x, acc.x); acc.y = fmaf(w1, hv1.y, acc.y);
        acc.z = fmaf(w1, hv1.z, acc.z); acc.w = fmaf(w1, hv1.w, acc.w);
    }
    if (e < e1) {
        int2 p = __ldg(&g_epack[e]);
        float w = __int_as_float(p.y);
        float4 hv = h4[(size_t)p.x * 16 + lane];
        acc.x = fmaf(w, hv.x, acc.x); acc.y = fmaf(w, hv.y, acc.y);
        acc.z = fmaf(w, hv.z, acc.z); acc.w = fmaf(w, hv.w, acc.w);
    }

    float sw = g_selfw[v];
    float4 hs = h4[(size_t)v * 16 + lane];
    float4 z  = ((const float4*)h0)[(size_t)v * 16 + lane];
    float4 r;
    r.x = fmaf(sw, hs.x, acc.x) + 0.1f * z.x;
    r.y = fmaf(sw, hs.y, acc.y) + 0.1f * z.y;
    r.z = fmaf(sw, hs.z, acc.z) + 0.1f * z.z;
    r.w = fmaf(sw, hs.w, acc.w) + 0.1f * z.w;
    ((float4*)hout)[(size_t)v * 16 + lane] = r;
}

// ---------------- launch ----------------
extern "C" void kernel_launch(void* const* d_in, const int* in_sizes, int n_in,
                              void* d_out, int out_size)
{
    const float* x  = (const float*)d_in[0];
    const int*   ei = (const int*)d_in[1];     // int32 [2, E]
    const float* w1 = (const float*)d_in[2];
    const float* b1 = (const float*)d_in[3];
    const float* w2 = (const float*)d_in[4];
    const float* b2 = (const float*)d_in[5];
    float*       out = (float*)d_out;

    float *p_hid, *p_h0, *p_htmp;
    cudaGetSymbolAddress((void**)&p_hid,  g_hid);
    cudaGetSymbolAddress((void**)&p_h0,   g_h0);
    cudaGetSymbolAddress((void**)&p_htmp, g_htmp);

    // graph preprocessing
    init_deg_cursor<<<(N_NODES + 255) / 256, 256>>>();
    count_deg<<<(N_EDGES + 255) / 256, 256>>>(ei);
    compute_dinv<<<(N_NODES + 255) / 256, 256>>>();
    scan_p1<<<NB_SCAN, 256>>>();
    scan_p2<<<1, 512>>>();
    scan_p3<<<NB_SCAN, 256>>>();
    fill_csr<<<(N_EDGES + 255) / 256, 256>>>(ei);

    // MLP: h0 = relu(x @ w1 + b1) @ w2 + b2
    dim3 g1((N_NODES + 127) / 128, HID_CH / 64);
    gemm_kernel<true><<<g1, 256>>>(x, w1, b1, p_hid, N_NODES, HID_CH, IN_CH);
    dim3 g2((N_NODES + 127) / 128, OUT_CH / 64);
    gemm_kernel<false><<<g2, 256>>>(p_hid, w2, b2, p_h0, N_NODES, OUT_CH, HID_CH);

    // APPNP propagation: K=10 steps, ping-pong so the last (odd) step hits d_out
    const float* cur = p_h0;
    int grid = (N_NODES * 16 + 255) / 256;
    for (int s = 0; s < K_STEPS; s++) {
        float* o = (s & 1) ? out : p_htmp;
        prop_kernel<<<grid, 256>>>(cur, o, p_h0);
        cur = o;
    }
}